// round 14
// baseline (speedup 1.0000x reference)
#include <cuda_runtime.h>
#include <cuda.h>
#include <cuda_fp16.h>
#include <cstdint>
#include <math.h>

#define BATCH 4
#define SEQ 4096
#define EMBED 1024
#define PROJ 128
#define MTOT (BATCH*SEQ)   // 16384

// tcgen05 is arch-specific: only for the sm_103a/sm_100a pass; the plain
// compute_103 PTX pass compiles empty GEMM bodies (never selected at run).
#if defined(__CUDA_ARCH__) && (defined(__CUDA_ARCH_FEAT_SM103_ALL) || defined(__CUDA_ARCH_FEAT_SM100_ALL))
#define TC_OK 1
#else
#define TC_OK 0
#endif

// ---------------- scratch (device globals; allocation-free) ----------------
__device__ __half g_x  [(size_t)MTOT*EMBED];      // 32 MB  x in fp16
__device__ __half g_QK [(size_t)MTOT*256];        // 8 MB   Q|K concat fp16
__device__ __half g_OVt[(size_t)EMBED*MTOT];      // 32 MB  OV^T fp16
__device__ __half g_S  [(size_t)BATCH*SEQ*SEQ];   // 128 MB E = exp(scores) fp16
__device__ float  g_R  [(size_t)MTOT*16];         // 1 MB   partial row sums
__device__ __half g_Wqk[256*EMBED];               // [Wq|Wk]^T fp16
__device__ float  g_bqk[256];
__device__ __half g_Wovt[(size_t)EMBED*EMBED];    // Wov^T fp16

// ---------------- tile config: stage = 128 bytes of K = 64 fp16 ------------
#define MT 128
#define NT 256
#define KB 64
#define ST 2
#define STAGE_A_BYTES (MT*128)
#define STAGE_B_BYTES (NT*128)
#define STAGE_BYTES   (STAGE_A_BYTES + STAGE_B_BYTES)
#define CTRL_BYTES    1024
#define SMEM_TOTAL    (CTRL_BYTES + ST*STAGE_BYTES)   // ~97 KB -> 2 CTAs/SM

// idesc kind::f16: dtype=F32(1)<<4, a/btype=F16(0), N/8<<17, M/16<<24
#define IDESC_F16 ((1u<<4) | ((NT/8u)<<17) | ((MT/16u)<<24))

__device__ __forceinline__ uint32_t smem_u32(const void* p) {
    uint32_t a;
    asm("{ .reg .u64 t; cvta.to.shared.u64 t, %1; cvt.u32.u64 %0, t; }" : "=r"(a) : "l"(p));
    return a;
}

#if TC_OK
// SW128 K-major smem descriptor: LBO=1, SBO=64, version=1, layout=2
__device__ __forceinline__ uint64_t make_desc(uint32_t addr) {
    const uint64_t base = (uint64_t(2) << 61) | (uint64_t(1) << 46)
                        | (uint64_t(64) << 32) | (uint64_t(1) << 16);
    return base | ((uint64_t)(addr >> 4) & 0x3FFF);
}

#define MBAR_INIT(a, c) \
    asm volatile("mbarrier.init.shared.b64 [%0], %1;" :: "r"(a), "r"(c) : "memory")
#define MBAR_EXPECT(a, b) \
    asm volatile("mbarrier.arrive.expect_tx.shared.b64 _, [%0], %1;" :: "r"(a), "r"(b) : "memory")
#define MBAR_WAIT(a, ph) do { \
    asm volatile("{\n\t.reg .pred P1;\n\t" \
        "WL_%=:\n\t" \
        "mbarrier.try_wait.parity.acquire.cta.shared::cta.b64 P1, [%0], %1, 0x989680;\n\t" \
        "@P1 bra WD_%=;\n\t" \
        "bra WL_%=;\n\t" \
        "WD_%=:\n\t}" \
        :: "r"(a), "r"(ph) : "memory"); \
} while (0)

__device__ __forceinline__ void tma2d(uint32_t dst, const CUtensorMap* m,
                                      int x, int y, uint32_t bar) {
    asm volatile(
        "cp.async.bulk.tensor.2d.shared::cta.global.tile.mbarrier::complete_tx::bytes "
        "[%0], [%1, {%2, %3}], [%4];"
        :: "r"(dst), "l"(m), "r"(x), "r"(y), "r"(bar) : "memory");
}

__device__ __forceinline__ void mma_f16(uint32_t d, uint64_t ad, uint64_t bd,
                                        uint32_t idesc, uint32_t en) {
    asm volatile(
        "{\n\t.reg .pred p;\n\tsetp.ne.u32 p, %4, 0;\n\t"
        "tcgen05.mma.cta_group::1.kind::f16 [%0], %1, %2, %3, {%5, %5, %5, %5}, p;\n\t}"
        :: "r"(d), "l"(ad), "l"(bd), "r"(idesc), "r"(en), "r"(0u) : "memory");
}

#define TC_COMMIT(bar) \
    asm volatile("tcgen05.commit.cta_group::1.mbarrier::arrive::one.shared::cluster.b64 [%0];" \
                 :: "r"(bar) : "memory")
#define TC_ALLOC(slot, n) \
    asm volatile("tcgen05.alloc.cta_group::1.sync.aligned.shared::cta.b32 [%0], %1;" \
                 :: "r"(slot), "r"(n) : "memory")
#define TC_DEALLOC(t, n) \
    asm volatile("tcgen05.dealloc.cta_group::1.sync.aligned.b32 %0, %1;" :: "r"(t), "r"(n))
#define TC_RELINQ() \
    asm volatile("tcgen05.relinquish_alloc_permit.cta_group::1.sync.aligned;")
#define TC_FENCE_AFTER()  asm volatile("tcgen05.fence::after_thread_sync;" ::: "memory")
#define TC_FENCE_BEFORE() asm volatile("tcgen05.fence::before_thread_sync;" ::: "memory")
#define TC_WAIT_LD()      asm volatile("tcgen05.wait::ld.sync.aligned;" ::: "memory")

#define TC_LD_X32(r, addr) \
    asm volatile( \
        "tcgen05.ld.sync.aligned.32x32b.x32.b32 " \
        "{%0, %1, %2, %3, %4, %5, %6, %7, " \
        " %8, %9, %10, %11, %12, %13, %14, %15, " \
        " %16, %17, %18, %19, %20, %21, %22, %23, " \
        " %24, %25, %26, %27, %28, %29, %30, %31}, [%32];" \
        : "=r"((r)[0]),  "=r"((r)[1]),  "=r"((r)[2]),  "=r"((r)[3]), \
          "=r"((r)[4]),  "=r"((r)[5]),  "=r"((r)[6]),  "=r"((r)[7]), \
          "=r"((r)[8]),  "=r"((r)[9]),  "=r"((r)[10]), "=r"((r)[11]), \
          "=r"((r)[12]), "=r"((r)[13]), "=r"((r)[14]), "=r"((r)[15]), \
          "=r"((r)[16]), "=r"((r)[17]), "=r"((r)[18]), "=r"((r)[19]), \
          "=r"((r)[20]), "=r"((r)[21]), "=r"((r)[22]), "=r"((r)[23]), \
          "=r"((r)[24]), "=r"((r)[25]), "=r"((r)[26]), "=r"((r)[27]), \
          "=r"((r)[28]), "=r"((r)[29]), "=r"((r)[30]), "=r"((r)[31]) \
        : "r"(addr))
#endif  // TC_OK

// ---------------------------------------------------------------------------
// tcgen05 fp16 GEMM: C[128x256 tile] = alpha * A @ B^T (+bias)
// outMode: 0 = f32 row-major (optionally scaled by 1/rowsum via rsumIn)
//          2 = f16 row-major
//          3 = f16 transposed
//          4 = f16 row-major exp(alpha*acc), partial row sums -> rsumOut
// ---------------------------------------------------------------------------
__global__ void __launch_bounds__(256, 2) tc_gemm(
    const __grid_constant__ CUtensorMap mapA,
    const __grid_constant__ CUtensorMap mapB,
    const float* __restrict__ bias, void* __restrict__ Cv,
    float* __restrict__ rsumOut, const float* __restrict__ rsumIn,
    int K, int xA0, int xB0, int szBx, int szAy, int szBy,
    int ldc, long szC, float alpha, int outMode)
{
#if TC_OK
    extern __shared__ __align__(1024) char smem[];
    const uint32_t sb = smem_u32(smem);
    const int tid = threadIdx.x, wid = tid >> 5;
    const int z = blockIdx.z;
    const int KT = K / KB;

    if (tid == 0) {
        #pragma unroll
        for (int s = 0; s < ST; s++) {
            MBAR_INIT(sb + s*16,     1);   // full
            MBAR_INIT(sb + s*16 + 8, 1);   // empty
        }
        MBAR_INIT(sb + 64, 1);             // done
    }
    if (wid == 0) TC_ALLOC(sb + 96, 256);
    __syncthreads();
    uint32_t tmem;
    asm volatile("ld.shared.b32 %0, [%1];" : "=r"(tmem) : "r"(sb + 96));

    if (tid == 224) {
        // ---- producer ----
        const int yA = blockIdx.y * MT + z * szAy;
        const int yB = blockIdx.x * NT + z * szBy;
        const int xB = xB0 + z * szBx;
        int s = 0, ph = 1;
        for (int kt = 0; kt < KT; kt++) {
            MBAR_WAIT(sb + s*16 + 8, ph);
            MBAR_EXPECT(sb + s*16, STAGE_BYTES);
            const uint32_t stg = sb + CTRL_BYTES + s * STAGE_BYTES;
            tma2d(stg,                 &mapA, xA0 + kt*KB, yA, sb + s*16);
            tma2d(stg + STAGE_A_BYTES, &mapB, xB  + kt*KB, yB, sb + s*16);
            if (++s == ST) { s = 0; ph ^= 1; }
        }
    } else if (tid == 192) {
        // ---- MMA issuer: 4 x K=16 per 64-K stage ----
        uint64_t ad[ST], bd[ST];
        #pragma unroll
        for (int s = 0; s < ST; s++) {
            ad[s] = make_desc(sb + CTRL_BYTES + s * STAGE_BYTES);
            bd[s] = make_desc(sb + CTRL_BYTES + s * STAGE_BYTES + STAGE_A_BYTES);
        }
        int s = 0, ph = 0;
        for (int kt = 0; kt < KT; kt++) {
            MBAR_WAIT(sb + s*16, ph);
            #pragma unroll
            for (int j = 0; j < 4; j++)
                mma_f16(tmem, ad[s] + j*2, bd[s] + j*2, IDESC_F16,
                        (uint32_t)((kt | j) != 0));
            TC_COMMIT(sb + s*16 + 8);
            if (++s == ST) { s = 0; ph ^= 1; }
        }
        TC_COMMIT(sb + 64);
    }

    MBAR_WAIT(sb + 64, 0);
    TC_FENCE_AFTER();

    // ---- epilogue: warps 0-3, lane m = tid (0..127) ----
    if (wid < 4) {
        const int ml = tid;
        float inv = 1.f;
        if (outMode == 0 && rsumIn) {
            const int q = z * szAy + blockIdx.y * MT + ml;   // szAy==SEQ here
            const float4* rp = (const float4*)(rsumIn + (long)q * 16);
            float4 a = rp[0], b = rp[1], c = rp[2], d = rp[3];
            inv = 1.f / (a.x+a.y+a.z+a.w + b.x+b.y+b.z+b.w
                       + c.x+c.y+c.z+c.w + d.x+d.y+d.z+d.w);
        }
        float rs = 0.f;
        #pragma unroll
        for (int nc = 0; nc < NT/32; nc++) {
            uint32_t r[32];
            TC_LD_X32(r, tmem + nc*32);
            TC_WAIT_LD();
            const int nbase = blockIdx.x * NT + nc * 32;
            if (outMode == 0) {                       // f32 row-major (final out)
                float* Cz = (float*)Cv + (long)z * szC;
                float4* dst = (float4*)(Cz + ((long)blockIdx.y*MT + ml) * ldc + nbase);
                #pragma unroll
                for (int j = 0; j < 8; j++) {
                    float4 bv = make_float4(0.f, 0.f, 0.f, 0.f);
                    if (bias) bv = *(const float4*)(bias + nbase + 4*j);
                    float4 o;
                    o.x = inv * __uint_as_float(r[4*j+0]) + bv.x;
                    o.y = inv * __uint_as_float(r[4*j+1]) + bv.y;
                    o.z = inv * __uint_as_float(r[4*j+2]) + bv.z;
                    o.w = inv * __uint_as_float(r[4*j+3]) + bv.w;
                    dst[j] = o;
                }
            } else if (outMode == 2) {                // f16 row-major (QK proj)
                __half* Cz = (__half*)Cv + (long)z * szC;
                uint32_t p[16];
                #pragma unroll
                for (int j = 0; j < 16; j++) {
                    float lo = alpha * __uint_as_float(r[2*j+0]);
                    float hi = alpha * __uint_as_float(r[2*j+1]);
                    if (bias) { lo += __ldg(bias + nbase + 2*j); hi += __ldg(bias + nbase + 2*j + 1); }
                    __half2 h = __floats2half2_rn(lo, hi);
                    p[j] = *(uint32_t*)&h;
                }
                uint4* dst = (uint4*)(Cz + ((long)blockIdx.y*MT + ml) * ldc + nbase);
                #pragma unroll
                for (int q = 0; q < 4; q++)
                    dst[q] = make_uint4(p[4*q], p[4*q+1], p[4*q+2], p[4*q+3]);
            } else if (outMode == 4) {                // E = exp(scale*s), + row sums
                __half* Cz = (__half*)Cv + (long)z * szC;
                uint32_t p[16];
                #pragma unroll
                for (int j = 0; j < 16; j++) {
                    float lo = __expf(alpha * __uint_as_float(r[2*j+0]));
                    float hi = __expf(alpha * __uint_as_float(r[2*j+1]));
                    rs += lo + hi;
                    __half2 h = __floats2half2_rn(lo, hi);
                    p[j] = *(uint32_t*)&h;
                }
                uint4* dst = (uint4*)(Cz + ((long)blockIdx.y*MT + ml) * ldc + nbase);
                #pragma unroll
                for (int q = 0; q < 4; q++)
                    dst[q] = make_uint4(p[4*q], p[4*q+1], p[4*q+2], p[4*q+3]);
            } else {                                  // f16 transposed (OV^T)
                __half* Cz = (__half*)Cv + (long)z * szC;
                #pragma unroll
                for (int i = 0; i < 32; i++) {
                    const int n = nbase + i;
                    float v = alpha * __uint_as_float(r[i]) + (bias ? __ldg(bias + n) : 0.f);
                    Cz[(long)n * ldc + blockIdx.y*MT + ml] = __float2half_rn(v);
                }
            }
        }
        if (outMode == 4) {
            const int q = z * szAy + blockIdx.y * MT + ml;   // global row
            rsumOut[(long)q * 16 + blockIdx.x] = rs;
        }
        TC_FENCE_BEFORE();
    }
    __syncthreads();
    if (wid == 0) { TC_RELINQ(); TC_DEALLOC(tmem, 256); }
#endif  // TC_OK
}

// ---------------- x -> fp16 copy -------------------------------------------
__global__ void __launch_bounds__(256) cvt_x(const float* __restrict__ x)
{
    const size_t i = ((size_t)blockIdx.x * 256 + threadIdx.x) * 8;
    float4 a = *(const float4*)(x + i);
    float4 b = *(const float4*)(x + i + 4);
    __half2 h0 = __floats2half2_rn(a.x, a.y);
    __half2 h1 = __floats2half2_rn(a.z, a.w);
    __half2 h2 = __floats2half2_rn(b.x, b.y);
    __half2 h3 = __floats2half2_rn(b.z, b.w);
    uint4 o = make_uint4(*(uint32_t*)&h0, *(uint32_t*)&h1,
                         *(uint32_t*)&h2, *(uint32_t*)&h3);
    *(uint4*)(g_x + i) = o;
}

// ---------------- weight prep: transpose + concat -> fp16 ------------------
__global__ void __launch_bounds__(256) prep_weights(
    const float* __restrict__ Wq, const float* __restrict__ bq,
    const float* __restrict__ Wk, const float* __restrict__ bk,
    const float* __restrict__ Wov)
{
    const int r = blockIdx.x, t = threadIdx.x;
    if (r < 256) {
        const int n = r & 127;
        const float* W = (r < 128) ? Wq : Wk;
        for (int e = t; e < EMBED; e += 256)
            g_Wqk[r*EMBED + e] = __float2half_rn(W[(long)e*PROJ + n]);
        if (t == 0) g_bqk[r] = (r < 128) ? bq[n] : bk[n];
    } else {
        const int n = r - 256;
        for (int e = t; e < EMBED; e += 256)
            g_Wovt[(long)n*EMBED + e] = __float2half_rn(Wov[(long)e*EMBED + n]);
    }
}

// ---------------- host ----------------
typedef CUresult (CUDAAPI *tmap_fn_t)(
    CUtensorMap*, CUtensorMapDataType, cuuint32_t, void*,
    const cuuint64_t*, const cuuint64_t*, const cuuint32_t*, const cuuint32_t*,
    CUtensorMapInterleave, CUtensorMapSwizzle, CUtensorMapL2promotion,
    CUtensorMapFloatOOBfill);

static void make_map(tmap_fn_t fn, CUtensorMap* m, void* base,
                     uint64_t d0, uint64_t d1, uint32_t b0, uint32_t b1)
{
    cuuint64_t dims[2]    = {d0, d1};
    cuuint64_t strides[1] = {d0 * 2};
    cuuint32_t box[2]     = {b0, b1};
    cuuint32_t es[2]      = {1, 1};
    fn(m, CU_TENSOR_MAP_DATA_TYPE_FLOAT16, 2, base, dims, strides, box, es,
       CU_TENSOR_MAP_INTERLEAVE_NONE, CU_TENSOR_MAP_SWIZZLE_128B,
       CU_TENSOR_MAP_L2_PROMOTION_L2_128B, CU_TENSOR_MAP_FLOAT_OOB_FILL_NONE);
}

extern "C" void kernel_launch(void* const* d_in, const int* in_sizes, int n_in,
                              void* d_out, int out_size)
{
    const float* x   = (const float*)d_in[0];
    const float* Wq  = (const float*)d_in[1];
    const float* bq  = (const float*)d_in[2];
    const float* Wk  = (const float*)d_in[3];
    const float* bk  = (const float*)d_in[4];
    const float* Wov = (const float*)d_in[5];
    const float* bov = (const float*)d_in[6];
    float* out = (float*)d_out;

    __half *xh, *QK, *OVt, *S, *Wqk, *Wovt;
    float *bqk, *R;
    cudaGetSymbolAddress((void**)&xh,   g_x);
    cudaGetSymbolAddress((void**)&QK,   g_QK);
    cudaGetSymbolAddress((void**)&OVt,  g_OVt);
    cudaGetSymbolAddress((void**)&S,    g_S);
    cudaGetSymbolAddress((void**)&R,    g_R);
    cudaGetSymbolAddress((void**)&Wqk,  g_Wqk);
    cudaGetSymbolAddress((void**)&bqk,  g_bqk);
    cudaGetSymbolAddress((void**)&Wovt, g_Wovt);

    cudaFuncSetAttribute(tc_gemm, cudaFuncAttributeMaxDynamicSharedMemorySize, SMEM_TOTAL);

    tmap_fn_t enc = nullptr;
    cudaDriverEntryPointQueryResult qr;
    cudaGetDriverEntryPointByVersion("cuTensorMapEncodeTiled", (void**)&enc,
                                     12000, cudaEnableDefault, &qr);

    CUtensorMap mX_A, mWqk_B, mWovt_B, mQK_A, mQK_B, mS_A, mOVt_B;
    make_map(enc, &mX_A,    xh,   1024, 16384, 64, 128);
    make_map(enc, &mWqk_B,  Wqk,  1024,   256, 64, 256);
    make_map(enc, &mWovt_B, Wovt, 1024,  1024, 64, 256);
    make_map(enc, &mQK_A,   QK,    256, 16384, 64, 128);
    make_map(enc, &mQK_B,   QK,    256, 16384, 64, 256);
    make_map(enc, &mS_A,    S,    4096, 16384, 64, 128);
    make_map(enc, &mOVt_B,  OVt, 16384,  1024, 64, 256);

    const float scale = 0.08838834764831845f;   // 1/sqrt(128)

    cvt_x<<<MTOT*EMBED/(256*8), 256>>>(x);
    prep_weights<<<1280, 256>>>(Wq, bq, Wk, bk, Wov);

    // QK = x @ [Wq|Wk] + [bq|bk]  -> g_QK fp16 [16384 x 256]
    tc_gemm<<<dim3(1, 128, 1), 256, SMEM_TOTAL>>>(
        mX_A, mWqk_B, bqk, QK, nullptr, nullptr,
        1024, 0, 0, 0, 0, 0, 256, 0, 1.f, 2);

    // OV^T = (x @ Wov + bov)^T   -> g_OVt fp16 [1024 x 16384]
    tc_gemm<<<dim3(4, 128, 1), 256, SMEM_TOTAL>>>(
        mX_A, mWovt_B, bov, OVt, nullptr, nullptr,
        1024, 0, 0, 0, 0, 0, 16384, 0, 1.f, 3);

    // E[b] = exp(scale * Q[b] @ K[b]^T) -> g_S fp16, partial row sums -> g_R
    tc_gemm<<<dim3(16, 32, 4), 256, SMEM_TOTAL>>>(
        mQK_A, mQK_B, nullptr, S, R, nullptr,
        128, 0, 128, 0, 4096, 4096, 4096, (long)SEQ * SEQ, scale, 4);

    // out[b] = (E[b] @ OV[b]) / rowsum  -> fp32 out
    tc_gemm<<<dim3(4, 32, 4), 256, SMEM_TOTAL>>>(
        mS_A, mOVt_B, nullptr, out, nullptr, R,
        4096, 0, 0, 4096, 4096, 0, 1024, (long)SEQ * EMBED, 1.f, 0);
}

// round 16
// speedup vs baseline: 1.7131x; 1.7131x over previous
#include <cuda_runtime.h>
#include <cuda.h>
#include <cuda_fp16.h>
#include <cstdint>
#include <math.h>

#define BATCH 4
#define SEQ 4096
#define EMBED 1024
#define PROJ 128
#define MTOT (BATCH*SEQ)   // 16384

// tcgen05 is arch-specific: only for the sm_103a/sm_100a pass; the plain
// compute_103 PTX pass compiles empty GEMM bodies (never selected at run).
#if defined(__CUDA_ARCH__) && (defined(__CUDA_ARCH_FEAT_SM103_ALL) || defined(__CUDA_ARCH_FEAT_SM100_ALL))
#define TC_OK 1
#else
#define TC_OK 0
#endif

// ---------------- scratch (device globals; allocation-free) ----------------
__device__ __half g_x  [(size_t)MTOT*EMBED];      // 32 MB  x in fp16
__device__ __half g_QK [(size_t)MTOT*256];        // 8 MB   Q|K concat fp16
__device__ __half g_OVt[(size_t)EMBED*MTOT];      // 32 MB  OV^T fp16
__device__ __half g_S  [(size_t)BATCH*SEQ*SEQ];   // 128 MB E = exp(scores) fp16
__device__ float  g_R  [(size_t)MTOT*16];         // 1 MB   partial row sums
__device__ __half g_Wqk[256*EMBED];               // [Wq|Wk]^T fp16
__device__ float  g_bqk[256];
__device__ __half g_Wovt[(size_t)EMBED*EMBED];    // Wov^T fp16

// ---------------- tile config: stage = 128 bytes of K = 64 fp16 ------------
#define MT 128
#define NT 256
#define KB 64
#define ST 4
#define STAGE_A_BYTES (MT*128)
#define STAGE_B_BYTES (NT*128)
#define STAGE_BYTES   (STAGE_A_BYTES + STAGE_B_BYTES)
#define CTRL_BYTES    1024
#define SMEM_TOTAL    (CTRL_BYTES + ST*STAGE_BYTES)   // ~197 KB, 1 CTA/SM

// idesc kind::f16: dtype=F32(1)<<4, a/btype=F16(0), N/8<<17, M/16<<24
#define IDESC_F16 ((1u<<4) | ((NT/8u)<<17) | ((MT/16u)<<24))

__device__ __forceinline__ uint32_t smem_u32(const void* p) {
    uint32_t a;
    asm("{ .reg .u64 t; cvta.to.shared.u64 t, %1; cvt.u32.u64 %0, t; }" : "=r"(a) : "l"(p));
    return a;
}

#if TC_OK
// SW128 K-major smem descriptor: LBO=1, SBO=64, version=1, layout=2
__device__ __forceinline__ uint64_t make_desc(uint32_t addr) {
    const uint64_t base = (uint64_t(2) << 61) | (uint64_t(1) << 46)
                        | (uint64_t(64) << 32) | (uint64_t(1) << 16);
    return base | ((uint64_t)(addr >> 4) & 0x3FFF);
}

#define MBAR_INIT(a, c) \
    asm volatile("mbarrier.init.shared.b64 [%0], %1;" :: "r"(a), "r"(c) : "memory")
#define MBAR_EXPECT(a, b) \
    asm volatile("mbarrier.arrive.expect_tx.shared.b64 _, [%0], %1;" :: "r"(a), "r"(b) : "memory")
#define MBAR_WAIT(a, ph) do { \
    asm volatile("{\n\t.reg .pred P1;\n\t" \
        "WL_%=:\n\t" \
        "mbarrier.try_wait.parity.acquire.cta.shared::cta.b64 P1, [%0], %1, 0x989680;\n\t" \
        "@P1 bra WD_%=;\n\t" \
        "bra WL_%=;\n\t" \
        "WD_%=:\n\t}" \
        :: "r"(a), "r"(ph) : "memory"); \
} while (0)

__device__ __forceinline__ void tma2d(uint32_t dst, const CUtensorMap* m,
                                      int x, int y, uint32_t bar) {
    asm volatile(
        "cp.async.bulk.tensor.2d.shared::cta.global.tile.mbarrier::complete_tx::bytes "
        "[%0], [%1, {%2, %3}], [%4];"
        :: "r"(dst), "l"(m), "r"(x), "r"(y), "r"(bar) : "memory");
}

__device__ __forceinline__ void mma_f16(uint32_t d, uint64_t ad, uint64_t bd,
                                        uint32_t idesc, uint32_t en) {
    asm volatile(
        "{\n\t.reg .pred p;\n\tsetp.ne.u32 p, %4, 0;\n\t"
        "tcgen05.mma.cta_group::1.kind::f16 [%0], %1, %2, %3, {%5, %5, %5, %5}, p;\n\t}"
        :: "r"(d), "l"(ad), "l"(bd), "r"(idesc), "r"(en), "r"(0u) : "memory");
}

#define TC_COMMIT(bar) \
    asm volatile("tcgen05.commit.cta_group::1.mbarrier::arrive::one.shared::cluster.b64 [%0];" \
                 :: "r"(bar) : "memory")
#define TC_ALLOC(slot, n) \
    asm volatile("tcgen05.alloc.cta_group::1.sync.aligned.shared::cta.b32 [%0], %1;" \
                 :: "r"(slot), "r"(n) : "memory")
#define TC_DEALLOC(t, n) \
    asm volatile("tcgen05.dealloc.cta_group::1.sync.aligned.b32 %0, %1;" :: "r"(t), "r"(n))
#define TC_RELINQ() \
    asm volatile("tcgen05.relinquish_alloc_permit.cta_group::1.sync.aligned;")
#define TC_FENCE_AFTER()  asm volatile("tcgen05.fence::after_thread_sync;" ::: "memory")
#define TC_FENCE_BEFORE() asm volatile("tcgen05.fence::before_thread_sync;" ::: "memory")
#define TC_WAIT_LD()      asm volatile("tcgen05.wait::ld.sync.aligned;" ::: "memory")

#define TC_LD_X32(r, addr) \
    asm volatile( \
        "tcgen05.ld.sync.aligned.32x32b.x32.b32 " \
        "{%0, %1, %2, %3, %4, %5, %6, %7, " \
        " %8, %9, %10, %11, %12, %13, %14, %15, " \
        " %16, %17, %18, %19, %20, %21, %22, %23, " \
        " %24, %25, %26, %27, %28, %29, %30, %31}, [%32];" \
        : "=r"((r)[0]),  "=r"((r)[1]),  "=r"((r)[2]),  "=r"((r)[3]), \
          "=r"((r)[4]),  "=r"((r)[5]),  "=r"((r)[6]),  "=r"((r)[7]), \
          "=r"((r)[8]),  "=r"((r)[9]),  "=r"((r)[10]), "=r"((r)[11]), \
          "=r"((r)[12]), "=r"((r)[13]), "=r"((r)[14]), "=r"((r)[15]), \
          "=r"((r)[16]), "=r"((r)[17]), "=r"((r)[18]), "=r"((r)[19]), \
          "=r"((r)[20]), "=r"((r)[21]), "=r"((r)[22]), "=r"((r)[23]), \
          "=r"((r)[24]), "=r"((r)[25]), "=r"((r)[26]), "=r"((r)[27]), \
          "=r"((r)[28]), "=r"((r)[29]), "=r"((r)[30]), "=r"((r)[31]) \
        : "r"(addr))
#endif  // TC_OK

// ---------------------------------------------------------------------------
// tcgen05 fp16 GEMM: C[128x256 tile] = alpha * A @ B^T (+bias)
// outMode: 0 = f32 row-major (optionally scaled by 1/rowsum via rsumIn)
//          2 = f16 row-major
//          3 = f16 transposed
//          4 = f16 row-major exp(alpha*acc), partial row sums -> rsumOut
// ---------------------------------------------------------------------------
__global__ void __launch_bounds__(256, 1) tc_gemm(
    const __grid_constant__ CUtensorMap mapA,
    const __grid_constant__ CUtensorMap mapB,
    const float* __restrict__ bias, void* __restrict__ Cv,
    float* __restrict__ rsumOut, const float* __restrict__ rsumIn,
    int K, int xA0, int xB0, int szBx, int szAy, int szBy,
    int ldc, long szC, float alpha, int outMode)
{
#if TC_OK
    extern __shared__ __align__(1024) char smem[];
    const uint32_t sb = smem_u32(smem);
    const int tid = threadIdx.x, wid = tid >> 5;
    const int z = blockIdx.z;
    const int KT = K / KB;

    if (tid == 0) {
        #pragma unroll
        for (int s = 0; s < ST; s++) {
            MBAR_INIT(sb + s*16,     1);   // full
            MBAR_INIT(sb + s*16 + 8, 1);   // empty
        }
        MBAR_INIT(sb + 64, 1);             // done
    }
    if (wid == 0) TC_ALLOC(sb + 96, 256);
    __syncthreads();
    uint32_t tmem;
    asm volatile("ld.shared.b32 %0, [%1];" : "=r"(tmem) : "r"(sb + 96));

    if (tid == 224) {
        // ---- producer ----
        const int yA = blockIdx.y * MT + z * szAy;
        const int yB = blockIdx.x * NT + z * szBy;
        const int xB = xB0 + z * szBx;
        int s = 0, ph = 1;
        for (int kt = 0; kt < KT; kt++) {
            MBAR_WAIT(sb + s*16 + 8, ph);
            MBAR_EXPECT(sb + s*16, STAGE_BYTES);
            const uint32_t stg = sb + CTRL_BYTES + s * STAGE_BYTES;
            tma2d(stg,                 &mapA, xA0 + kt*KB, yA, sb + s*16);
            tma2d(stg + STAGE_A_BYTES, &mapB, xB  + kt*KB, yB, sb + s*16);
            if (++s == ST) { s = 0; ph ^= 1; }
        }
    } else if (tid == 192) {
        // ---- MMA issuer: 4 x K=16 per 64-K stage ----
        uint64_t ad[ST], bd[ST];
        #pragma unroll
        for (int s = 0; s < ST; s++) {
            ad[s] = make_desc(sb + CTRL_BYTES + s * STAGE_BYTES);
            bd[s] = make_desc(sb + CTRL_BYTES + s * STAGE_BYTES + STAGE_A_BYTES);
        }
        int s = 0, ph = 0;
        for (int kt = 0; kt < KT; kt++) {
            MBAR_WAIT(sb + s*16, ph);
            #pragma unroll
            for (int j = 0; j < 4; j++)
                mma_f16(tmem, ad[s] + j*2, bd[s] + j*2, IDESC_F16,
                        (uint32_t)((kt | j) != 0));
            TC_COMMIT(sb + s*16 + 8);
            if (++s == ST) { s = 0; ph ^= 1; }
        }
        TC_COMMIT(sb + 64);
    }

    MBAR_WAIT(sb + 64, 0);
    TC_FENCE_AFTER();

    // ---- epilogue: warps 0-3, lane m = tid (0..127) ----
    if (wid < 4) {
        const int ml = tid;
        float inv = 1.f;
        if (outMode == 0 && rsumIn) {
            const int q = z * szAy + blockIdx.y * MT + ml;   // szAy==SEQ here
            const float4* rp = (const float4*)(rsumIn + (long)q * 16);
            float4 a = rp[0], b = rp[1], c = rp[2], d = rp[3];
            inv = 1.f / (a.x+a.y+a.z+a.w + b.x+b.y+b.z+b.w
                       + c.x+c.y+c.z+c.w + d.x+d.y+d.z+d.w);
        }
        float rs = 0.f;
        #pragma unroll
        for (int nc = 0; nc < NT/32; nc++) {
            uint32_t r[32];
            TC_LD_X32(r, tmem + nc*32);
            TC_WAIT_LD();
            const int nbase = blockIdx.x * NT + nc * 32;
            if (outMode == 0) {                       // f32 row-major (final out)
                float* Cz = (float*)Cv + (long)z * szC;
                float4* dst = (float4*)(Cz + ((long)blockIdx.y*MT + ml) * ldc + nbase);
                #pragma unroll
                for (int j = 0; j < 8; j++) {
                    float4 bv = make_float4(0.f, 0.f, 0.f, 0.f);
                    if (bias) bv = *(const float4*)(bias + nbase + 4*j);
                    float4 o;
                    o.x = inv * __uint_as_float(r[4*j+0]) + bv.x;
                    o.y = inv * __uint_as_float(r[4*j+1]) + bv.y;
                    o.z = inv * __uint_as_float(r[4*j+2]) + bv.z;
                    o.w = inv * __uint_as_float(r[4*j+3]) + bv.w;
                    dst[j] = o;
                }
            } else if (outMode == 2) {                // f16 row-major (QK proj)
                __half* Cz = (__half*)Cv + (long)z * szC;
                uint32_t p[16];
                #pragma unroll
                for (int j = 0; j < 16; j++) {
                    float lo = alpha * __uint_as_float(r[2*j+0]);
                    float hi = alpha * __uint_as_float(r[2*j+1]);
                    if (bias) { lo += __ldg(bias + nbase + 2*j); hi += __ldg(bias + nbase + 2*j + 1); }
                    __half2 h = __floats2half2_rn(lo, hi);
                    p[j] = *(uint32_t*)&h;
                }
                uint4* dst = (uint4*)(Cz + ((long)blockIdx.y*MT + ml) * ldc + nbase);
                #pragma unroll
                for (int q = 0; q < 4; q++)
                    dst[q] = make_uint4(p[4*q], p[4*q+1], p[4*q+2], p[4*q+3]);
            } else if (outMode == 4) {                // E = exp(scale*s), + row sums
                __half* Cz = (__half*)Cv + (long)z * szC;
                uint32_t p[16];
                #pragma unroll
                for (int j = 0; j < 16; j++) {
                    float lo = __expf(alpha * __uint_as_float(r[2*j+0]));
                    float hi = __expf(alpha * __uint_as_float(r[2*j+1]));
                    rs += lo + hi;
                    __half2 h = __floats2half2_rn(lo, hi);
                    p[j] = *(uint32_t*)&h;
                }
                uint4* dst = (uint4*)(Cz + ((long)blockIdx.y*MT + ml) * ldc + nbase);
                #pragma unroll
                for (int q = 0; q < 4; q++)
                    dst[q] = make_uint4(p[4*q], p[4*q+1], p[4*q+2], p[4*q+3]);
            } else {                                  // f16 transposed (OV^T)
                __half* Cz = (__half*)Cv + (long)z * szC;
                #pragma unroll
                for (int i = 0; i < 32; i++) {
                    const int n = nbase + i;
                    float v = alpha * __uint_as_float(r[i]) + (bias ? __ldg(bias + n) : 0.f);
                    Cz[(long)n * ldc + blockIdx.y*MT + ml] = __float2half_rn(v);
                }
            }
        }
        if (outMode == 4) {
            const int q = z * szAy + blockIdx.y * MT + ml;   // global row
            rsumOut[(long)q * 16 + blockIdx.x] = rs;
        }
        TC_FENCE_BEFORE();
    }
    __syncthreads();
    if (wid == 0) { TC_RELINQ(); TC_DEALLOC(tmem, 256); }
#endif  // TC_OK
}

// ---------------- x -> fp16 copy -------------------------------------------
__global__ void __launch_bounds__(256) cvt_x(const float* __restrict__ x)
{
    const size_t i = ((size_t)blockIdx.x * 256 + threadIdx.x) * 8;
    float4 a = *(const float4*)(x + i);
    float4 b = *(const float4*)(x + i + 4);
    __half2 h0 = __floats2half2_rn(a.x, a.y);
    __half2 h1 = __floats2half2_rn(a.z, a.w);
    __half2 h2 = __floats2half2_rn(b.x, b.y);
    __half2 h3 = __floats2half2_rn(b.z, b.w);
    uint4 o = make_uint4(*(uint32_t*)&h0, *(uint32_t*)&h1,
                         *(uint32_t*)&h2, *(uint32_t*)&h3);
    *(uint4*)(g_x + i) = o;
}

// ---------------- weight prep: transpose + concat -> fp16 ------------------
__global__ void __launch_bounds__(256) prep_weights(
    const float* __restrict__ Wq, const float* __restrict__ bq,
    const float* __restrict__ Wk, const float* __restrict__ bk,
    const float* __restrict__ Wov)
{
    const int r = blockIdx.x, t = threadIdx.x;
    if (r < 256) {
        const int n = r & 127;
        const float* W = (r < 128) ? Wq : Wk;
        for (int e = t; e < EMBED; e += 256)
            g_Wqk[r*EMBED + e] = __float2half_rn(W[(long)e*PROJ + n]);
        if (t == 0) g_bqk[r] = (r < 128) ? bq[n] : bk[n];
    } else {
        const int n = r - 256;
        for (int e = t; e < EMBED; e += 256)
            g_Wovt[(long)n*EMBED + e] = __float2half_rn(Wov[(long)e*EMBED + n]);
    }
}

// ---------------- host ----------------
typedef CUresult (CUDAAPI *tmap_fn_t)(
    CUtensorMap*, CUtensorMapDataType, cuuint32_t, void*,
    const cuuint64_t*, const cuuint64_t*, const cuuint32_t*, const cuuint32_t*,
    CUtensorMapInterleave, CUtensorMapSwizzle, CUtensorMapL2promotion,
    CUtensorMapFloatOOBfill);

static void make_map(tmap_fn_t fn, CUtensorMap* m, void* base,
                     uint64_t d0, uint64_t d1, uint32_t b0, uint32_t b1)
{
    cuuint64_t dims[2]    = {d0, d1};
    cuuint64_t strides[1] = {d0 * 2};
    cuuint32_t box[2]     = {b0, b1};
    cuuint32_t es[2]      = {1, 1};
    fn(m, CU_TENSOR_MAP_DATA_TYPE_FLOAT16, 2, base, dims, strides, box, es,
       CU_TENSOR_MAP_INTERLEAVE_NONE, CU_TENSOR_MAP_SWIZZLE_128B,
       CU_TENSOR_MAP_L2_PROMOTION_L2_128B, CU_TENSOR_MAP_FLOAT_OOB_FILL_NONE);
}

extern "C" void kernel_launch(void* const* d_in, const int* in_sizes, int n_in,
                              void* d_out, int out_size)
{
    const float* x   = (const float*)d_in[0];
    const float* Wq  = (const float*)d_in[1];
    const float* bq  = (const float*)d_in[2];
    const float* Wk  = (const float*)d_in[3];
    const float* bk  = (const float*)d_in[4];
    const float* Wov = (const float*)d_in[5];
    const float* bov = (const float*)d_in[6];
    float* out = (float*)d_out;

    __half *xh, *QK, *OVt, *S, *Wqk, *Wovt;
    float *bqk, *R;
    cudaGetSymbolAddress((void**)&xh,   g_x);
    cudaGetSymbolAddress((void**)&QK,   g_QK);
    cudaGetSymbolAddress((void**)&OVt,  g_OVt);
    cudaGetSymbolAddress((void**)&S,    g_S);
    cudaGetSymbolAddress((void**)&R,    g_R);
    cudaGetSymbolAddress((void**)&Wqk,  g_Wqk);
    cudaGetSymbolAddress((void**)&bqk,  g_bqk);
    cudaGetSymbolAddress((void**)&Wovt, g_Wovt);

    cudaFuncSetAttribute(tc_gemm, cudaFuncAttributeMaxDynamicSharedMemorySize, SMEM_TOTAL);

    tmap_fn_t enc = nullptr;
    cudaDriverEntryPointQueryResult qr;
    cudaGetDriverEntryPointByVersion("cuTensorMapEncodeTiled", (void**)&enc,
                                     12000, cudaEnableDefault, &qr);

    CUtensorMap mX_A, mWqk_B, mWovt_B, mQK_A, mQK_B, mS_A, mOVt_B;
    make_map(enc, &mX_A,    xh,   1024, 16384, 64, 128);
    make_map(enc, &mWqk_B,  Wqk,  1024,   256, 64, 256);
    make_map(enc, &mWovt_B, Wovt, 1024,  1024, 64, 256);
    make_map(enc, &mQK_A,   QK,    256, 16384, 64, 128);
    make_map(enc, &mQK_B,   QK,    256, 16384, 64, 256);
    make_map(enc, &mS_A,    S,    4096, 16384, 64, 128);
    make_map(enc, &mOVt_B,  OVt, 16384,  1024, 64, 256);

    const float scale = 0.08838834764831845f;   // 1/sqrt(128)

    cvt_x<<<MTOT*EMBED/(256*8), 256>>>(x);
    prep_weights<<<1280, 256>>>(Wq, bq, Wk, bk, Wov);

    // QK = x @ [Wq|Wk] + [bq|bk]  -> g_QK fp16 [16384 x 256]
    tc_gemm<<<dim3(1, 128, 1), 256, SMEM_TOTAL>>>(
        mX_A, mWqk_B, bqk, QK, nullptr, nullptr,
        1024, 0, 0, 0, 0, 0, 256, 0, 1.f, 2);

    // OV^T = (x @ Wov + bov)^T   -> g_OVt fp16 [1024 x 16384]
    tc_gemm<<<dim3(4, 128, 1), 256, SMEM_TOTAL>>>(
        mX_A, mWovt_B, bov, OVt, nullptr, nullptr,
        1024, 0, 0, 0, 0, 0, 16384, 0, 1.f, 3);

    // E[b] = exp(scale * Q[b] @ K[b]^T) -> g_S fp16, partial row sums -> g_R
    tc_gemm<<<dim3(16, 32, 4), 256, SMEM_TOTAL>>>(
        mQK_A, mQK_B, nullptr, S, R, nullptr,
        128, 0, 128, 0, 4096, 4096, 4096, (long)SEQ * SEQ, scale, 4);

    // out[b] = (E[b] @ OV[b]) / rowsum  -> fp32 out
    tc_gemm<<<dim3(4, 32, 4), 256, SMEM_TOTAL>>>(
        mS_A, mOVt_B, nullptr, out, nullptr, R,
        4096, 0, 0, 4096, 4096, 0, 1024, (long)SEQ * EMBED, 1.f, 0);
}

// round 17
// speedup vs baseline: 2.0470x; 1.1949x over previous
#include <cuda_runtime.h>
#include <cuda.h>
#include <cuda_fp16.h>
#include <cstdint>
#include <math.h>

#define BATCH 4
#define SEQ 4096
#define EMBED 1024
#define PROJ 128
#define MTOT (BATCH*SEQ)   // 16384

#if defined(__CUDA_ARCH__) && (defined(__CUDA_ARCH_FEAT_SM103_ALL) || defined(__CUDA_ARCH_FEAT_SM100_ALL))
#define TC_OK 1
#else
#define TC_OK 0
#endif

// ---------------- scratch (device globals; allocation-free) ----------------
__device__ __half g_x  [(size_t)MTOT*EMBED];      // 32 MB  x in fp16
__device__ __half g_QK [(size_t)MTOT*256];        // 8 MB   Q|K concat fp16
__device__ __half g_OVt[(size_t)EMBED*MTOT];      // 32 MB  OV^T fp16
__device__ __half g_S  [(size_t)BATCH*SEQ*SEQ];   // 128 MB E = exp(scores) fp16
__device__ float  g_R  [(size_t)MTOT*16];         // 1 MB   partial row sums
__device__ __half g_Wqk[256*EMBED];               // [Wq|Wk]^T fp16
__device__ float  g_bqk[256];
__device__ __half g_Wovt[(size_t)EMBED*EMBED];    // Wov^T fp16

// ---------------- tile config: stage = 128 bytes of K = 64 fp16 ------------
#define MT 128
#define NT 256
#define KB 64
#define ST 4
#define STAGE_A_BYTES (MT*128)
#define STAGE_B_BYTES (NT*128)
#define STAGE_BYTES   (STAGE_A_BYTES + STAGE_B_BYTES)
#define CTRL_BYTES    1024
#define SMEM_TOTAL    (CTRL_BYTES + ST*STAGE_BYTES)   // ~197 KB, 1 CTA/SM

// idesc kind::f16: dtype=F32(1)<<4, a/btype=F16(0), N/8<<17, M/16<<24
#define IDESC_F16 ((1u<<4) | ((NT/8u)<<17) | ((MT/16u)<<24))

__device__ __forceinline__ uint32_t smem_u32(const void* p) {
    uint32_t a;
    asm("{ .reg .u64 t; cvta.to.shared.u64 t, %1; cvt.u32.u64 %0, t; }" : "=r"(a) : "l"(p));
    return a;
}

#if TC_OK
// SW128 K-major smem descriptor: LBO=1, SBO=64, version=1, layout=2
__device__ __forceinline__ uint64_t make_desc(uint32_t addr) {
    const uint64_t base = (uint64_t(2) << 61) | (uint64_t(1) << 46)
                        | (uint64_t(64) << 32) | (uint64_t(1) << 16);
    return base | ((uint64_t)(addr >> 4) & 0x3FFF);
}

#define MBAR_INIT(a, c) \
    asm volatile("mbarrier.init.shared.b64 [%0], %1;" :: "r"(a), "r"(c) : "memory")
#define MBAR_EXPECT(a, b) \
    asm volatile("mbarrier.arrive.expect_tx.shared.b64 _, [%0], %1;" :: "r"(a), "r"(b) : "memory")
#define MBAR_ARRIVE(a) \
    asm volatile("mbarrier.arrive.shared.b64 _, [%0];" :: "r"(a) : "memory")
#define MBAR_WAIT(a, ph) do { \
    asm volatile("{\n\t.reg .pred P1;\n\t" \
        "WL_%=:\n\t" \
        "mbarrier.try_wait.parity.acquire.cta.shared::cta.b64 P1, [%0], %1, 0x989680;\n\t" \
        "@P1 bra WD_%=;\n\t" \
        "bra WL_%=;\n\t" \
        "WD_%=:\n\t}" \
        :: "r"(a), "r"(ph) : "memory"); \
} while (0)

__device__ __forceinline__ void tma2d(uint32_t dst, const CUtensorMap* m,
                                      int x, int y, uint32_t bar) {
    asm volatile(
        "cp.async.bulk.tensor.2d.shared::cta.global.tile.mbarrier::complete_tx::bytes "
        "[%0], [%1, {%2, %3}], [%4];"
        :: "r"(dst), "l"(m), "r"(x), "r"(y), "r"(bar) : "memory");
}

__device__ __forceinline__ void mma_f16(uint32_t d, uint64_t ad, uint64_t bd,
                                        uint32_t idesc, uint32_t en) {
    asm volatile(
        "{\n\t.reg .pred p;\n\tsetp.ne.u32 p, %4, 0;\n\t"
        "tcgen05.mma.cta_group::1.kind::f16 [%0], %1, %2, %3, {%5, %5, %5, %5}, p;\n\t}"
        :: "r"(d), "l"(ad), "l"(bd), "r"(idesc), "r"(en), "r"(0u) : "memory");
}

#define TC_COMMIT(bar) \
    asm volatile("tcgen05.commit.cta_group::1.mbarrier::arrive::one.shared::cluster.b64 [%0];" \
                 :: "r"(bar) : "memory")
#define TC_ALLOC(slot, n) \
    asm volatile("tcgen05.alloc.cta_group::1.sync.aligned.shared::cta.b32 [%0], %1;" \
                 :: "r"(slot), "r"(n) : "memory")
#define TC_DEALLOC(t, n) \
    asm volatile("tcgen05.dealloc.cta_group::1.sync.aligned.b32 %0, %1;" :: "r"(t), "r"(n))
#define TC_RELINQ() \
    asm volatile("tcgen05.relinquish_alloc_permit.cta_group::1.sync.aligned;")
#define TC_FENCE_AFTER()  asm volatile("tcgen05.fence::after_thread_sync;" ::: "memory")
#define TC_FENCE_BEFORE() asm volatile("tcgen05.fence::before_thread_sync;" ::: "memory")
#define TC_WAIT_LD()      asm volatile("tcgen05.wait::ld.sync.aligned;" ::: "memory")

#define TC_LD_X32(r, addr) \
    asm volatile( \
        "tcgen05.ld.sync.aligned.32x32b.x32.b32 " \
        "{%0, %1, %2, %3, %4, %5, %6, %7, " \
        " %8, %9, %10, %11, %12, %13, %14, %15, " \
        " %16, %17, %18, %19, %20, %21, %22, %23, " \
        " %24, %25, %26, %27, %28, %29, %30, %31}, [%32];" \
        : "=r"((r)[0]),  "=r"((r)[1]),  "=r"((r)[2]),  "=r"((r)[3]), \
          "=r"((r)[4]),  "=r"((r)[5]),  "=r"((r)[6]),  "=r"((r)[7]), \
          "=r"((r)[8]),  "=r"((r)[9]),  "=r"((r)[10]), "=r"((r)[11]), \
          "=r"((r)[12]), "=r"((r)[13]), "=r"((r)[14]), "=r"((r)[15]), \
          "=r"((r)[16]), "=r"((r)[17]), "=r"((r)[18]), "=r"((r)[19]), \
          "=r"((r)[20]), "=r"((r)[21]), "=r"((r)[22]), "=r"((r)[23]), \
          "=r"((r)[24]), "=r"((r)[25]), "=r"((r)[26]), "=r"((r)[27]), \
          "=r"((r)[28]), "=r"((r)[29]), "=r"((r)[30]), "=r"((r)[31]) \
        : "r"(addr))
#endif  // TC_OK

// ---------------------------------------------------------------------------
// Persistent tcgen05 fp16 GEMM with TMEM ping-pong (epilogue/mainloop overlap)
// Tiles t = blockIdx.x + i*gridDim.x, t -> (tx, ty, tz) with tx fastest.
// outMode: 0 = f32 row-major (/rowsum via rsumIn)
//          2 = f16 row-major
//          3 = f16 transposed
//          4 = f16 row-major exp(alpha*acc), partial row sums -> rsumOut
// ---------------------------------------------------------------------------
__global__ void __launch_bounds__(256, 1) tc_gemm(
    const __grid_constant__ CUtensorMap mapA,
    const __grid_constant__ CUtensorMap mapB,
    const float* __restrict__ bias, void* __restrict__ Cv,
    float* __restrict__ rsumOut, const float* __restrict__ rsumIn,
    int K, int T, int gx, int gy,
    int xA0, int xB0, int szBx, int szAy, int szBy,
    int ldc, long szC, float alpha, int outMode)
{
#if TC_OK
    extern __shared__ __align__(1024) char smem[];
    const uint32_t sb = smem_u32(smem);
    const int tid = threadIdx.x, wid = tid >> 5;
    const int G = gridDim.x;
    const int KT = K / KB;

    // ctrl: full[s]@s*16, empty[s]@s*16+8, done[p]@64+p*16, epi_free[p]@64+p*16+8,
    // tmem-slot @96
    if (tid == 0) {
        #pragma unroll
        for (int s = 0; s < ST; s++) {
            MBAR_INIT(sb + s*16,     1);     // full
            MBAR_INIT(sb + s*16 + 8, 1);     // empty
        }
        #pragma unroll
        for (int p = 0; p < 2; p++) {
            MBAR_INIT(sb + 64 + p*16,     1);    // done[p]
            MBAR_INIT(sb + 64 + p*16 + 8, 128);  // epi_free[p]
        }
    }
    if (wid == 0) TC_ALLOC(sb + 96, 512);
    __syncthreads();
    uint32_t tmem;
    asm volatile("ld.shared.b32 %0, [%1];" : "=r"(tmem) : "r"(sb + 96));

    if (tid == 224) {
        // ---- producer: continuous TMA ring across tiles ----
        int g = 0;
        for (int t = blockIdx.x; t < T; t += G) {
            const int tx = t % gx, tyz = t / gx;
            const int ty = tyz % gy, tz = tyz / gy;
            const int yA = ty * MT + tz * szAy;
            const int yB = tx * NT + tz * szBy;
            const int xB = xB0 + tz * szBx;
            for (int kt = 0; kt < KT; kt++, g++) {
                const int s = g & (ST-1);
                const int ph = ((g >> 2) & 1) ^ 1;
                MBAR_WAIT(sb + s*16 + 8, ph);            // empty
                MBAR_EXPECT(sb + s*16, STAGE_BYTES);
                const uint32_t stg = sb + CTRL_BYTES + s * STAGE_BYTES;
                tma2d(stg,                 &mapA, xA0 + kt*KB, yA, sb + s*16);
                tma2d(stg + STAGE_A_BYTES, &mapB, xB  + kt*KB, yB, sb + s*16);
            }
        }
    } else if (tid == 192) {
        // ---- MMA issuer: ping-pong D buffers ----
        uint64_t ad[ST], bd[ST];
        #pragma unroll
        for (int s = 0; s < ST; s++) {
            ad[s] = make_desc(sb + CTRL_BYTES + s * STAGE_BYTES);
            bd[s] = make_desc(sb + CTRL_BYTES + s * STAGE_BYTES + STAGE_A_BYTES);
        }
        int g = 0, i = 0;
        for (int t = blockIdx.x; t < T; t += G, i++) {
            const int p = i & 1, u = i >> 1;
            if (u > 0) {                                  // wait epilogue drained buf p
                MBAR_WAIT(sb + 64 + p*16 + 8, (u-1) & 1);
                TC_FENCE_AFTER();
            }
            const uint32_t d = tmem + p * 256;
            for (int kt = 0; kt < KT; kt++, g++) {
                const int s = g & (ST-1);
                MBAR_WAIT(sb + s*16, (g >> 2) & 1);       // full
                #pragma unroll
                for (int j = 0; j < 4; j++)
                    mma_f16(d, ad[s] + j*2, bd[s] + j*2, IDESC_F16,
                            (uint32_t)((kt | j) != 0));
                TC_COMMIT(sb + s*16 + 8);                 // -> empty[s]
            }
            TC_COMMIT(sb + 64 + p*16);                    // -> done[p]
        }
    }

    // ---- epilogue: warps 0-3, lane m = tid (0..127) ----
    if (wid < 4) {
        const int ml = tid;
        int i = 0;
        for (int t = blockIdx.x; t < T; t += G, i++) {
            const int p = i & 1;
            MBAR_WAIT(sb + 64 + p*16, (i >> 1) & 1);      // done[p]
            TC_FENCE_AFTER();
            const uint32_t dbase = tmem + p * 256;

            const int tx = t % gx, tyz = t / gx;
            const int ty = tyz % gy, tz = tyz / gy;

            float inv = 1.f;
            if (outMode == 0 && rsumIn) {
                const int q = tz * szAy + ty * MT + ml;
                const float4* rp = (const float4*)(rsumIn + (long)q * 16);
                float4 a = rp[0], b = rp[1], c = rp[2], d4 = rp[3];
                inv = 1.f / (a.x+a.y+a.z+a.w + b.x+b.y+b.z+b.w
                           + c.x+c.y+c.z+c.w + d4.x+d4.y+d4.z+d4.w);
            }
            float rs = 0.f;
            #pragma unroll
            for (int nc = 0; nc < NT/32; nc++) {
                uint32_t r[32];
                TC_LD_X32(r, dbase + nc*32);
                TC_WAIT_LD();
                const int nbase = tx * NT + nc * 32;
                if (outMode == 0) {                       // f32 row-major (final out)
                    float* Cz = (float*)Cv + (long)tz * szC;
                    float4* dst = (float4*)(Cz + ((long)ty*MT + ml) * ldc + nbase);
                    #pragma unroll
                    for (int j = 0; j < 8; j++) {
                        float4 bv = make_float4(0.f, 0.f, 0.f, 0.f);
                        if (bias) bv = *(const float4*)(bias + nbase + 4*j);
                        float4 o;
                        o.x = inv * __uint_as_float(r[4*j+0]) + bv.x;
                        o.y = inv * __uint_as_float(r[4*j+1]) + bv.y;
                        o.z = inv * __uint_as_float(r[4*j+2]) + bv.z;
                        o.w = inv * __uint_as_float(r[4*j+3]) + bv.w;
                        dst[j] = o;
                    }
                } else if (outMode == 2) {                // f16 row-major (QK proj)
                    __half* Cz = (__half*)Cv + (long)tz * szC;
                    uint32_t pk[16];
                    #pragma unroll
                    for (int j = 0; j < 16; j++) {
                        float lo = alpha * __uint_as_float(r[2*j+0]);
                        float hi = alpha * __uint_as_float(r[2*j+1]);
                        if (bias) { lo += __ldg(bias + nbase + 2*j); hi += __ldg(bias + nbase + 2*j + 1); }
                        __half2 h = __floats2half2_rn(lo, hi);
                        pk[j] = *(uint32_t*)&h;
                    }
                    uint4* dst = (uint4*)(Cz + ((long)ty*MT + ml) * ldc + nbase);
                    #pragma unroll
                    for (int q = 0; q < 4; q++)
                        dst[q] = make_uint4(pk[4*q], pk[4*q+1], pk[4*q+2], pk[4*q+3]);
                } else if (outMode == 4) {                // E = exp(scale*s), + row sums
                    __half* Cz = (__half*)Cv + (long)tz * szC;
                    uint32_t pk[16];
                    #pragma unroll
                    for (int j = 0; j < 16; j++) {
                        float lo = __expf(alpha * __uint_as_float(r[2*j+0]));
                        float hi = __expf(alpha * __uint_as_float(r[2*j+1]));
                        rs += lo + hi;
                        __half2 h = __floats2half2_rn(lo, hi);
                        pk[j] = *(uint32_t*)&h;
                    }
                    uint4* dst = (uint4*)(Cz + ((long)ty*MT + ml) * ldc + nbase);
                    #pragma unroll
                    for (int q = 0; q < 4; q++)
                        dst[q] = make_uint4(pk[4*q], pk[4*q+1], pk[4*q+2], pk[4*q+3]);
                } else {                                  // f16 transposed (OV^T)
                    __half* Cz = (__half*)Cv + (long)tz * szC;
                    #pragma unroll
                    for (int idx = 0; idx < 32; idx++) {
                        const int n = nbase + idx;
                        float v = alpha * __uint_as_float(r[idx]) + (bias ? __ldg(bias + n) : 0.f);
                        Cz[(long)n * ldc + ty*MT + ml] = __float2half_rn(v);
                    }
                }
            }
            if (outMode == 4) {
                const int q = tz * szAy + ty * MT + ml;
                rsumOut[(long)q * 16 + tx] = rs;
            }
            TC_FENCE_BEFORE();
            MBAR_ARRIVE(sb + 64 + p*16 + 8);              // -> epi_free[p]
        }
    }
    __syncthreads();
    if (wid == 0) { TC_RELINQ(); TC_DEALLOC(tmem, 512); }
#endif  // TC_OK
}

// ---------------- x -> fp16 copy -------------------------------------------
__global__ void __launch_bounds__(256) cvt_x(const float* __restrict__ x)
{
    const size_t i = ((size_t)blockIdx.x * 256 + threadIdx.x) * 8;
    float4 a = *(const float4*)(x + i);
    float4 b = *(const float4*)(x + i + 4);
    __half2 h0 = __floats2half2_rn(a.x, a.y);
    __half2 h1 = __floats2half2_rn(a.z, a.w);
    __half2 h2 = __floats2half2_rn(b.x, b.y);
    __half2 h3 = __floats2half2_rn(b.z, b.w);
    uint4 o = make_uint4(*(uint32_t*)&h0, *(uint32_t*)&h1,
                         *(uint32_t*)&h2, *(uint32_t*)&h3);
    *(uint4*)(g_x + i) = o;
}

// ---------------- weight prep: transpose + concat -> fp16 ------------------
__global__ void __launch_bounds__(256) prep_weights(
    const float* __restrict__ Wq, const float* __restrict__ bq,
    const float* __restrict__ Wk, const float* __restrict__ bk,
    const float* __restrict__ Wov)
{
    const int r = blockIdx.x, t = threadIdx.x;
    if (r < 256) {
        const int n = r & 127;
        const float* W = (r < 128) ? Wq : Wk;
        for (int e = t; e < EMBED; e += 256)
            g_Wqk[r*EMBED + e] = __float2half_rn(W[(long)e*PROJ + n]);
        if (t == 0) g_bqk[r] = (r < 128) ? bq[n] : bk[n];
    } else {
        const int n = r - 256;
        for (int e = t; e < EMBED; e += 256)
            g_Wovt[(long)n*EMBED + e] = __float2half_rn(Wov[(long)e*EMBED + n]);
    }
}

// ---------------- host ----------------
typedef CUresult (CUDAAPI *tmap_fn_t)(
    CUtensorMap*, CUtensorMapDataType, cuuint32_t, void*,
    const cuuint64_t*, const cuuint64_t*, const cuuint32_t*, const cuuint32_t*,
    CUtensorMapInterleave, CUtensorMapSwizzle, CUtensorMapL2promotion,
    CUtensorMapFloatOOBfill);

static void make_map(tmap_fn_t fn, CUtensorMap* m, void* base,
                     uint64_t d0, uint64_t d1, uint32_t b0, uint32_t b1)
{
    cuuint64_t dims[2]    = {d0, d1};
    cuuint64_t strides[1] = {d0 * 2};
    cuuint32_t box[2]     = {b0, b1};
    cuuint32_t es[2]      = {1, 1};
    fn(m, CU_TENSOR_MAP_DATA_TYPE_FLOAT16, 2, base, dims, strides, box, es,
       CU_TENSOR_MAP_INTERLEAVE_NONE, CU_TENSOR_MAP_SWIZZLE_128B,
       CU_TENSOR_MAP_L2_PROMOTION_L2_128B, CU_TENSOR_MAP_FLOAT_OOB_FILL_NONE);
}

extern "C" void kernel_launch(void* const* d_in, const int* in_sizes, int n_in,
                              void* d_out, int out_size)
{
    const float* x   = (const float*)d_in[0];
    const float* Wq  = (const float*)d_in[1];
    const float* bq  = (const float*)d_in[2];
    const float* Wk  = (const float*)d_in[3];
    const float* bk  = (const float*)d_in[4];
    const float* Wov = (const float*)d_in[5];
    const float* bov = (const float*)d_in[6];
    float* out = (float*)d_out;

    __half *xh, *QK, *OVt, *S, *Wqk, *Wovt;
    float *bqk, *R;
    cudaGetSymbolAddress((void**)&xh,   g_x);
    cudaGetSymbolAddress((void**)&QK,   g_QK);
    cudaGetSymbolAddress((void**)&OVt,  g_OVt);
    cudaGetSymbolAddress((void**)&S,    g_S);
    cudaGetSymbolAddress((void**)&R,    g_R);
    cudaGetSymbolAddress((void**)&Wqk,  g_Wqk);
    cudaGetSymbolAddress((void**)&bqk,  g_bqk);
    cudaGetSymbolAddress((void**)&Wovt, g_Wovt);

    cudaFuncSetAttribute(tc_gemm, cudaFuncAttributeMaxDynamicSharedMemorySize, SMEM_TOTAL);

    tmap_fn_t enc = nullptr;
    cudaDriverEntryPointQueryResult qr;
    cudaGetDriverEntryPointByVersion("cuTensorMapEncodeTiled", (void**)&enc,
                                     12000, cudaEnableDefault, &qr);

    CUtensorMap mX_A, mWqk_B, mWovt_B, mQK_A, mQK_B, mS_A, mOVt_B;
    make_map(enc, &mX_A,    xh,   1024, 16384, 64, 128);
    make_map(enc, &mWqk_B,  Wqk,  1024,   256, 64, 256);
    make_map(enc, &mWovt_B, Wovt, 1024,  1024, 64, 256);
    make_map(enc, &mQK_A,   QK,    256, 16384, 64, 128);
    make_map(enc, &mQK_B,   QK,    256, 16384, 64, 256);
    make_map(enc, &mS_A,    S,    4096, 16384, 64, 128);
    make_map(enc, &mOVt_B,  OVt, 16384,  1024, 64, 256);

    const float scale = 0.08838834764831845f;   // 1/sqrt(128)

    cvt_x<<<MTOT*EMBED/(256*8), 256>>>(x);
    prep_weights<<<1280, 256>>>(Wq, bq, Wk, bk, Wov);

    auto G = [](int T) { return T < 148 ? T : 148; };

    // QK = x @ [Wq|Wk] + [bq|bk]  -> g_QK fp16 [16384 x 256]   (T=128)
    tc_gemm<<<G(128), 256, SMEM_TOTAL>>>(
        mX_A, mWqk_B, bqk, QK, nullptr, nullptr,
        1024, 128, 1, 128, 0, 0, 0, 0, 0, 256, 0, 1.f, 2);

    // OV^T = (x @ Wov + bov)^T   -> g_OVt fp16 [1024 x 16384]  (T=512)
    tc_gemm<<<G(512), 256, SMEM_TOTAL>>>(
        mX_A, mWovt_B, bov, OVt, nullptr, nullptr,
        1024, 512, 4, 128, 0, 0, 0, 0, 0, 16384, 0, 1.f, 3);

    // E[b] = exp(scale * Q[b] @ K[b]^T) -> g_S fp16, row sums -> g_R (T=2048)
    tc_gemm<<<G(2048), 256, SMEM_TOTAL>>>(
        mQK_A, mQK_B, nullptr, S, R, nullptr,
        128, 2048, 16, 32, 0, 128, 0, 4096, 4096, 4096, (long)SEQ * SEQ, scale, 4);

    // out[b] = (E[b] @ OV[b]) / rowsum  -> fp32 out            (T=512)
    tc_gemm<<<G(512), 256, SMEM_TOTAL>>>(
        mS_A, mOVt_B, nullptr, out, nullptr, R,
        4096, 512, 4, 32, 0, 0, 4096, 4096, 0, 1024, (long)SEQ * EMBED, 1.f, 0);
}